// round 8
// baseline (speedup 1.0000x reference)
#include <cuda_runtime.h>
#include <cstdint>
#include <cstddef>

#define NTOK 8192
#define CDIM 512

// ---------------- scratch (device globals; no allocations allowed) ----------
__device__ __align__(16) float g_S1[(size_t)NTOK * NTOK];
__device__ __align__(16) float g_S2[(size_t)NTOK * NTOK];
__device__ __align__(16) float g_QK1[(size_t)NTOK * 128];
__device__ __align__(16) float g_QK2[(size_t)NTOK * 128];
__device__ __align__(16) float g_VT1[(size_t)CDIM * NTOK];   // V^T
__device__ __align__(16) float g_VT2[(size_t)CDIM * NTOK];   // V^T
__device__ __align__(16) float g_Wqk[(size_t)CDIM * 128];
__device__ __align__(16) float g_part[(size_t)2 * 64 * NTOK];
__device__ __align__(16) float g_rinv[2 * NTOK];

// ---------------- helpers ----------------------------------------------------
__device__ __forceinline__ uint32_t f2tf32(float x) {
    uint32_t r;
    asm("cvt.rna.tf32.f32 %0, %1;" : "=r"(r) : "f"(x));
    return r;
}
__device__ __forceinline__ float tf32_round(float x) { return __uint_as_float(f2tf32(x)); }

// truncate-to-tf32 split: hi = 1 LOP3 (alu), lo = 1 FADD (fma pipe)
__device__ __forceinline__ uint32_t tf32_hi(float x) {
    return __float_as_uint(x) & 0xFFFFE000u;
}

__device__ __forceinline__ void mma8(float* c, const uint32_t* a, const uint32_t* b) {
    asm volatile(
        "mma.sync.aligned.m16n8k8.row.col.f32.tf32.tf32.f32 "
        "{%0,%1,%2,%3}, {%4,%5,%6,%7}, {%8,%9}, {%0,%1,%2,%3};"
        : "+f"(c[0]), "+f"(c[1]), "+f"(c[2]), "+f"(c[3])
        : "r"(a[0]), "r"(a[1]), "r"(a[2]), "r"(a[3]), "r"(b[0]), "r"(b[1]));
}

__device__ __forceinline__ uint32_t s2u(const void* p) {
    return (uint32_t)__cvta_generic_to_shared(p);
}
__device__ __forceinline__ void cp16(uint32_t dst, const void* src) {
    asm volatile("cp.async.cg.shared.global [%0], [%1], 16;" :: "r"(dst), "l"(src) : "memory");
}

__global__ void pack_wqk(const float* __restrict__ Wq, const float* __restrict__ Wk,
                         float* __restrict__ Wqk) {
    const int i = blockIdx.x * 256 + threadIdx.x;   // 512*128
    const int r = i >> 7, c = i & 127;
    Wqk[i] = (c < 64) ? Wq[r * 64 + c] : Wk[r * 64 + (c - 64)];
}

// ================= 3xTF32 error-compensated GEMM =============================
// 256 threads, block 128x128, warp tile 64x32. z batches two problems.
// TRB=true : B row-major [K x N] (transposed into smem)  -- projections
// TRB=false: B row-major [N x K]                          -- logits (Q @ K^T)
// EXPSUM   : epilogue writes tf32(exp(acc)) and per-row partial sums to part.
template<bool TRB, bool EXPSUM>
__global__ __launch_bounds__(256, 2)
void gemm3x(const float* __restrict__ A0, const float* __restrict__ A1, int lda,
            const float* __restrict__ B0, const float* __restrict__ B1, int ldb,
            float* __restrict__ C0, float* __restrict__ C1, int ldc, int K,
            float* __restrict__ part)
{
    constexpr int BK = 16, STR = BK + 8;
    __shared__ float As[2][128][STR];
    __shared__ float Bs[2][128][STR];

    const int z = blockIdx.z;
    const float* A = z ? A1 : A0;
    const float* B = z ? B1 : B0;
    float*       C = z ? C1 : C0;

    const int tid  = threadIdx.x;
    const int lane = tid & 31;
    const int wid  = tid >> 5;
    const int wm0  = (wid & 1) << 6;
    const int wn0  = (wid >> 1) << 5;
    const int lr   = lane >> 2;
    const int lc2  = (lane & 3) << 1;

    const size_t row0 = (size_t)blockIdx.y * 128;
    const size_t col0 = (size_t)blockIdx.x * 128;

    const int ar = tid >> 2;
    const int ac = (tid & 3) << 2;
    const float* Ap0 = A + (row0 + ar) * (size_t)lda + ac;
    const float* Ap1 = Ap0 + (size_t)64 * lda;

    const float *Bp0, *Bp1;
    int bk_ = 0, bg4 = 0;
    if (TRB) {
        bk_ = tid & 15;
        bg4 = (tid >> 4) << 2;
        Bp0 = B + (size_t)bk_ * ldb + col0 + bg4;
        Bp1 = Bp0 + 64;
    } else {
        Bp0 = B + (col0 + ar) * (size_t)ldb + ac;
        Bp1 = Bp0 + (size_t)64 * ldb;
    }

    float4 a0 = *(const float4*)Ap0;
    float4 a1 = *(const float4*)Ap1;
    float4 b0 = *(const float4*)Bp0;
    float4 b1 = *(const float4*)Bp1;

    float acc[4][4][4];
#pragma unroll
    for (int i = 0; i < 4; i++)
#pragma unroll
        for (int j = 0; j < 4; j++)
#pragma unroll
            for (int k = 0; k < 4; k++) acc[i][j][k] = 0.f;

    auto store_tiles = [&](int bf, float4 sa0, float4 sa1, float4 sb0, float4 sb1) {
        *(float4*)&As[bf][ar][ac]      = sa0;
        *(float4*)&As[bf][ar + 64][ac] = sa1;
        if (TRB) {
            Bs[bf][bg4 + 0][bk_] = sb0.x;
            Bs[bf][bg4 + 1][bk_] = sb0.y;
            Bs[bf][bg4 + 2][bk_] = sb0.z;
            Bs[bf][bg4 + 3][bk_] = sb0.w;
            Bs[bf][bg4 + 64][bk_] = sb1.x;
            Bs[bf][bg4 + 65][bk_] = sb1.y;
            Bs[bf][bg4 + 66][bk_] = sb1.z;
            Bs[bf][bg4 + 67][bk_] = sb1.w;
        } else {
            *(float4*)&Bs[bf][ar][ac]      = sb0;
            *(float4*)&Bs[bf][ar + 64][ac] = sb1;
        }
    };

    auto compute = [&](int bf) {
#pragma unroll
        for (int kk = 0; kk < BK; kk += 8) {
            uint32_t ah[4][4], al[4][4], bh[4][2], bl[4][2];
#pragma unroll
            for (int mt = 0; mt < 4; mt++) {
                const float2 t0 = *(const float2*)&As[bf][wm0 + mt * 16 + lr][kk + lc2];
                const float2 t1 = *(const float2*)&As[bf][wm0 + mt * 16 + lr + 8][kk + lc2];
                ah[mt][0] = tf32_hi(t0.x); al[mt][0] = __float_as_uint(t0.x - __uint_as_float(ah[mt][0]));
                ah[mt][2] = tf32_hi(t0.y); al[mt][2] = __float_as_uint(t0.y - __uint_as_float(ah[mt][2]));
                ah[mt][1] = tf32_hi(t1.x); al[mt][1] = __float_as_uint(t1.x - __uint_as_float(ah[mt][1]));
                ah[mt][3] = tf32_hi(t1.y); al[mt][3] = __float_as_uint(t1.y - __uint_as_float(ah[mt][3]));
            }
#pragma unroll
            for (int nt = 0; nt < 4; nt++) {
                const float2 t = *(const float2*)&Bs[bf][wn0 + nt * 8 + lr][kk + lc2];
                bh[nt][0] = tf32_hi(t.x); bl[nt][0] = __float_as_uint(t.x - __uint_as_float(bh[nt][0]));
                bh[nt][1] = tf32_hi(t.y); bl[nt][1] = __float_as_uint(t.y - __uint_as_float(bh[nt][1]));
            }
#pragma unroll
            for (int mt = 0; mt < 4; mt++)
#pragma unroll
                for (int nt = 0; nt < 4; nt++) {
                    mma8(acc[mt][nt], ah[mt], bh[nt]);
                    mma8(acc[mt][nt], al[mt], bh[nt]);
                    mma8(acc[mt][nt], ah[mt], bl[nt]);
                }
        }
    };

    store_tiles(0, a0, a1, b0, b1);
    __syncthreads();

    const int KT = K / BK;
    int buf = 0;
    for (int t = 1; t <= KT; t++) {
        if (t < KT) {
            const int ko = t * BK;
            a0 = *(const float4*)(Ap0 + ko);
            a1 = *(const float4*)(Ap1 + ko);
            if (TRB) {
                b0 = *(const float4*)(Bp0 + (size_t)ko * ldb);
                b1 = *(const float4*)(Bp1 + (size_t)ko * ldb);
            } else {
                b0 = *(const float4*)(Bp0 + ko);
                b1 = *(const float4*)(Bp1 + ko);
            }
        }
        compute(buf);
        if (t < KT) {
            buf ^= 1;
            store_tiles(buf, a0, a1, b0, b1);
            __syncthreads();
        }
    }

    if (EXPSUM) {
        __syncthreads();                 // smem reads done; reuse As as scratch
        float* red = &As[0][0][0];
#pragma unroll
        for (int mt = 0; mt < 4; mt++) {
#pragma unroll
            for (int h = 0; h < 2; h++) {
                const int rl = wm0 + mt * 16 + lr + 8 * h;
                float* Crow = C + (row0 + rl) * (size_t)ldc + col0;
                float es = 0.f;
#pragma unroll
                for (int nt = 0; nt < 4; nt++) {
                    const int cc = wn0 + nt * 8 + lc2;
                    float2 v;
                    v.x = tf32_round(__expf(acc[mt][nt][h * 2 + 0]));
                    v.y = tf32_round(__expf(acc[mt][nt][h * 2 + 1]));
                    es += v.x + v.y;
                    *(float2*)(Crow + cc) = v;
                }
                es += __shfl_xor_sync(0xffffffffu, es, 1);
                es += __shfl_xor_sync(0xffffffffu, es, 2);
                if ((lane & 3) == 0) red[(wid >> 1) * 128 + rl] = es;
            }
        }
        __syncthreads();
        if (tid < 128) {
            const float s = red[tid] + red[128 + tid] + red[256 + tid] + red[384 + tid];
            part[((size_t)z * 64 + blockIdx.x) * NTOK + row0 + tid] = s;
        }
    } else {
#pragma unroll
        for (int mt = 0; mt < 4; mt++) {
#pragma unroll
            for (int h = 0; h < 2; h++) {
                const size_t r = row0 + wm0 + mt * 16 + lr + h * 8;
                float* Crow = C + r * (size_t)ldc + col0;
#pragma unroll
                for (int nt = 0; nt < 4; nt++) {
                    const int cc = wn0 + nt * 8 + lc2;
                    float2 v;
                    v.x = acc[mt][nt][h * 2 + 0];
                    v.y = acc[mt][nt][h * 2 + 1];
                    *(float2*)(Crow + cc) = v;
                }
            }
        }
    }
}

__global__ void reduce_rinv(const float* __restrict__ part, float* __restrict__ rinv) {
    const int i = blockIdx.x * 256 + threadIdx.x;   // 0..16383
    const int z = i >> 13, r = i & (NTOK - 1);
    const float* p = part + (size_t)z * 64 * NTOK + r;
    float s = 0.f;
#pragma unroll
    for (int b = 0; b < 64; b++) s += p[(size_t)b * NTOK];
    rinv[i] = 1.f / s;
}

// ================= V projection -> writes V^T (tf32-rounded) ================
// 128 threads, block 128x128 of V, warp tile 64x64, transposed-B smem.
// Output: VT[c * NTOK + r] = tf32(sum_k im[r,k] * Wv[k,c])  (operands tf32-rna)
__global__ __launch_bounds__(128, 2)
void vproj_gemm(const float* __restrict__ A0, const float* __restrict__ A1,
                const float* __restrict__ B,
                float* __restrict__ VT0, float* __restrict__ VT1)
{
    constexpr int STR = 24;
    __shared__ float As[2][128][STR];
    __shared__ float Bs[2][128][STR];

    const int z = blockIdx.z;
    const float* A = z ? A1 : A0;
    float*      VT = z ? VT1 : VT0;

    const int tid  = threadIdx.x;
    const int lane = tid & 31;
    const int wid  = tid >> 5;
    const int wm0  = (wid & 1) << 6;
    const int wn0  = (wid >> 1) << 6;
    const int lr   = lane >> 2;
    const int lc2  = (lane & 3) << 1;

    const size_t row0 = (size_t)blockIdx.y * 128;
    const size_t col0 = (size_t)blockIdx.x * 128;

    const int arr = tid >> 2;
    const int ac4 = (tid & 3) << 2;
    const float* Apb = A + (row0 + arr) * (size_t)CDIM + ac4;
    const size_t astr = (size_t)32 * CDIM;

    const int bk  = tid & 15;
    const int bn0 = (tid >> 4) << 4;
    const float* Bpb = B + (size_t)bk * CDIM + col0 + bn0;

    float acc[4][8][4];
#pragma unroll
    for (int i = 0; i < 4; i++)
#pragma unroll
        for (int j = 0; j < 8; j++)
#pragma unroll
            for (int k = 0; k < 4; k++) acc[i][j][k] = 0.f;

    auto stage = [&](int bf, const float4* av, const float4* bv) {
#pragma unroll
        for (int j = 0; j < 4; j++) {
            float4 v = av[j];
            v.x = tf32_round(v.x); v.y = tf32_round(v.y);
            v.z = tf32_round(v.z); v.w = tf32_round(v.w);
            *(float4*)&As[bf][arr + 32 * j][ac4] = v;
        }
#pragma unroll
        for (int i = 0; i < 4; i++) {
            float4 v = bv[i];
            v.x = tf32_round(v.x); v.y = tf32_round(v.y);
            v.z = tf32_round(v.z); v.w = tf32_round(v.w);
            const int nb = bn0 + 4 * i;
            Bs[bf][nb + 0][bk] = v.x;
            Bs[bf][nb + 1][bk] = v.y;
            Bs[bf][nb + 2][bk] = v.z;
            Bs[bf][nb + 3][bk] = v.w;
        }
    };

    float4 av[4], bv[4];
#pragma unroll
    for (int j = 0; j < 4; j++) av[j] = *(const float4*)(Apb + j * astr);
#pragma unroll
    for (int i = 0; i < 4; i++) bv[i] = *(const float4*)(Bpb + 4 * i);
    stage(0, av, bv);
    __syncthreads();

    const int KT = CDIM / 16;
    int buf = 0;
    for (int t = 1; t <= KT; t++) {
        if (t < KT) {
            const size_t ko = (size_t)t * 16;
#pragma unroll
            for (int j = 0; j < 4; j++) av[j] = *(const float4*)(Apb + j * astr + ko);
#pragma unroll
            for (int i = 0; i < 4; i++) bv[i] = *(const float4*)(Bpb + ko * CDIM + 4 * i);
        }
#pragma unroll
        for (int kk = 0; kk < 16; kk += 8) {
            uint32_t ah[4][4], bh[8][2];
#pragma unroll
            for (int mt = 0; mt < 4; mt++) {
                const float2 t0 = *(const float2*)&As[buf][wm0 + mt * 16 + lr][kk + lc2];
                const float2 t1 = *(const float2*)&As[buf][wm0 + mt * 16 + lr + 8][kk + lc2];
                ah[mt][0] = __float_as_uint(t0.x);
                ah[mt][1] = __float_as_uint(t1.x);
                ah[mt][2] = __float_as_uint(t0.y);
                ah[mt][3] = __float_as_uint(t1.y);
            }
#pragma unroll
            for (int nt = 0; nt < 8; nt++) {
                const float2 t = *(const float2*)&Bs[buf][wn0 + nt * 8 + lr][kk + lc2];
                bh[nt][0] = __float_as_uint(t.x);
                bh[nt][1] = __float_as_uint(t.y);
            }
#pragma unroll
            for (int mt = 0; mt < 4; mt++)
#pragma unroll
                for (int nt = 0; nt < 8; nt++)
                    mma8(acc[mt][nt], ah[mt], bh[nt]);
        }
        if (t < KT) {
            buf ^= 1;
            stage(buf, av, bv);
            __syncthreads();
        }
    }

    // transposed epilogue: VT[c][r]
#pragma unroll
    for (int mt = 0; mt < 4; mt++) {
#pragma unroll
        for (int h = 0; h < 2; h++) {
            const size_t r = row0 + wm0 + mt * 16 + lr + h * 8;
#pragma unroll
            for (int nt = 0; nt < 8; nt++) {
                const size_t cc = col0 + wn0 + nt * 8 + lc2;
                VT[cc * NTOK + r]       = tf32_round(acc[mt][nt][h * 2 + 0]);
                VT[(cc + 1) * NTOK + r] = tf32_round(acc[mt][nt][h * 2 + 1]);
            }
        }
    }
}

// ================= PV GEMM: 128x256 tile, cp.async 3-stage ===================
// A = S [NTOK x NTOK] (rows k-contig), B = V^T [CDIM x NTOK] (rows k-contig).
// Both staged by pure 16B cp.async into the proven STR=24 layouts.
// Epilogue: C = acc * rinv[row] + Res.
#define PV_STAGES 3
__global__ __launch_bounds__(256, 1)
void pv_gemm(const float* __restrict__ A0, const float* __restrict__ A1,
             const float* __restrict__ BT0, const float* __restrict__ BT1,
             const float* __restrict__ R0, const float* __restrict__ R1,
             float* __restrict__ C0, float* __restrict__ C1,
             const float* __restrict__ RI)
{
    constexpr int STR = 24;
    extern __shared__ float dsm[];
    float (*As)[128][STR] = (float (*)[128][STR])dsm;                        // [3][128][24]
    float (*Bs)[256][STR] = (float (*)[256][STR])(dsm + PV_STAGES * 128 * STR);

    const int z = blockIdx.z;
    const float* A   = z ? A1 : A0;
    const float* BT  = z ? BT1 : BT0;
    const float* Res = z ? R1 : R0;
    float*       C   = z ? C1 : C0;

    const int tid  = threadIdx.x;
    const int lane = tid & 31;
    const int wid  = tid >> 5;          // 0..7
    const int wm0  = (wid & 1) << 6;    // 0,64
    const int wn0  = (wid >> 1) << 6;   // 0,64,128,192
    const int lr   = lane >> 2;
    const int lc2  = (lane & 3) << 1;

    const size_t row0 = (size_t)blockIdx.y * 128;
    const size_t col0 = (size_t)blockIdx.x * 256;

    // A loader: row tid>>1, 8 floats at (tid&1)*8  -> 2 cp16
    const int arr = tid >> 1;
    const int ac8 = (tid & 1) << 3;
    const float* Apb = A + (row0 + arr) * (size_t)NTOK + ac8;
    // B loader: V^T row (col0 + tid), 16 floats -> 4 cp16
    const float* Bpb = BT + (col0 + tid) * (size_t)NTOK;

    float acc[4][8][4];
#pragma unroll
    for (int i = 0; i < 4; i++)
#pragma unroll
        for (int j = 0; j < 8; j++)
#pragma unroll
            for (int k = 0; k < 4; k++) acc[i][j][k] = 0.f;

    auto issue = [&](int t) {
        const int bf = t % PV_STAGES;
        const float* a = Apb + (size_t)t * 16;
        const uint32_t da = s2u(&As[bf][arr][ac8]);
        cp16(da, a);
        cp16(da + 16, a + 4);
        const float* b = Bpb + (size_t)t * 16;
        const uint32_t db = s2u(&Bs[bf][tid][0]);
        cp16(db, b);
        cp16(db + 16, b + 4);
        cp16(db + 32, b + 8);
        cp16(db + 48, b + 12);
        asm volatile("cp.async.commit_group;" ::: "memory");
    };

    const int KT = NTOK / 16;           // 512
    issue(0);
    issue(1);

    for (int t = 0; t < KT; t++) {
        if (t + 2 < KT) {
            issue(t + 2);
            asm volatile("cp.async.wait_group 2;" ::: "memory");
        } else if (t + 1 < KT) {
            asm volatile("cp.async.wait_group 1;" ::: "memory");
        } else {
            asm volatile("cp.async.wait_group 0;" ::: "memory");
        }
        __syncthreads();

        const int buf = t % PV_STAGES;
#pragma unroll
        for (int kk = 0; kk < 16; kk += 8) {
            uint32_t ah[4][4], bh[8][2];
#pragma unroll
            for (int mt = 0; mt < 4; mt++) {
                const float2 t0 = *(const float2*)&As[buf][wm0 + mt * 16 + lr][kk + lc2];
                const float2 t1 = *(const float2*)&As[buf][wm0 + mt * 16 + lr + 8][kk + lc2];
                ah[mt][0] = __float_as_uint(t0.x);
                ah[mt][1] = __float_as_uint(t1.x);
                ah[mt][2] = __float_as_uint(t0.y);
                ah[mt][3] = __float_as_uint(t1.y);
            }
#pragma unroll
            for (int nt = 0; nt < 8; nt++) {
                const float2 t2 = *(const float2*)&Bs[buf][wn0 + nt * 8 + lr][kk + lc2];
                bh[nt][0] = __float_as_uint(t2.x);
                bh[nt][1] = __float_as_uint(t2.y);
            }
#pragma unroll
            for (int mt = 0; mt < 4; mt++)
#pragma unroll
                for (int nt = 0; nt < 8; nt++)
                    mma8(acc[mt][nt], ah[mt], bh[nt]);
        }
        __syncthreads();
    }

    // epilogue: scale by rinv, add residual
#pragma unroll
    for (int mt = 0; mt < 4; mt++) {
#pragma unroll
        for (int h = 0; h < 2; h++) {
            const size_t r = row0 + wm0 + mt * 16 + lr + h * 8;
            const float scale = RI[(size_t)z * NTOK + r];
            float* Crow = C + r * (size_t)CDIM + col0;
            const float* Rrow = Res + r * (size_t)CDIM + col0;
#pragma unroll
            for (int nt = 0; nt < 8; nt++) {
                const int cc = wn0 + nt * 8 + lc2;
                const float2 rv = *(const float2*)(Rrow + cc);
                float2 v;
                v.x = acc[mt][nt][h * 2 + 0] * scale + rv.x;
                v.y = acc[mt][nt][h * 2 + 1] * scale + rv.y;
                *(float2*)(Crow + cc) = v;
            }
        }
    }
}

// ---------------- launch -----------------------------------------------------
extern "C" void kernel_launch(void* const* d_in, const int* in_sizes, int n_in,
                              void* d_out, int out_size)
{
    const float* im1 = (const float*)d_in[0];
    const float* im2 = (const float*)d_in[1];
    const float* Wq  = (const float*)d_in[2];
    const float* Wk  = (const float*)d_in[3];
    const float* Wv  = (const float*)d_in[4];

    float* out1 = (float*)d_out;
    float* out2 = out1 + (size_t)NTOK * CDIM;

    float *pS1, *pS2, *pQK1, *pQK2, *pVT1, *pVT2, *pWqk, *pPart, *pRinv;
    cudaGetSymbolAddress((void**)&pS1,   g_S1);
    cudaGetSymbolAddress((void**)&pS2,   g_S2);
    cudaGetSymbolAddress((void**)&pQK1,  g_QK1);
    cudaGetSymbolAddress((void**)&pQK2,  g_QK2);
    cudaGetSymbolAddress((void**)&pVT1,  g_VT1);
    cudaGetSymbolAddress((void**)&pVT2,  g_VT2);
    cudaGetSymbolAddress((void**)&pWqk,  g_Wqk);
    cudaGetSymbolAddress((void**)&pPart, g_part);
    cudaGetSymbolAddress((void**)&pRinv, g_rinv);

    const int PV_SMEM = PV_STAGES * (128 * 24 + 256 * 24) * 4;   // 110592 B
    static bool attr_set = false;
    if (!attr_set) {
        cudaFuncSetAttribute(pv_gemm, cudaFuncAttributeMaxDynamicSharedMemorySize, PV_SMEM);
        attr_set = true;
    }

    pack_wqk<<<256, 256>>>(Wq, Wk, pWqk);

    // Q/K projections (3xTF32, near-fp32): [Q|K]z = imz @ [Wq|Wk]
    gemm3x<true, false><<<dim3(1, 64, 2), 256>>>(im1, im2, CDIM, pWqk, pWqk, 128,
                                                 pQK1, pQK2, 128, CDIM, nullptr);
    // V projections -> V^T (single-pass tf32, rna staging, rounded outputs)
    vproj_gemm<<<dim3(4, 64, 2), 128>>>(im1, im2, Wv, pVT1, pVT2);
    // logits + fused exp + partial row sums: S1 = exp(Q2 K1^T), S2 = exp(Q1 K2^T)
    gemm3x<false, true><<<dim3(64, 64, 2), 256>>>(pQK2, pQK1, 128, pQK1 + 64, pQK2 + 64, 128,
                                                  pS1, pS2, NTOK, 64, pPart);
    reduce_rinv<<<64, 256>>>(pPart, pRinv);
    // PV: out = (S @ V) * rinv + im   (cp.async pipeline, 128x256 tiles)
    pv_gemm<<<dim3(2, 64, 2), 256, PV_SMEM>>>(pS1, pS2, pVT1, pVT2,
                                              im1, im2, out1, out2, pRinv);
}

// round 10
// speedup vs baseline: 1.0115x; 1.0115x over previous
#include <cuda_runtime.h>
#include <cstdint>
#include <cstddef>

#define NTOK 8192
#define CDIM 512

// ---------------- scratch (device globals; no allocations allowed) ----------
__device__ __align__(16) float g_S1[(size_t)NTOK * NTOK];
__device__ __align__(16) float g_S2[(size_t)NTOK * NTOK];
__device__ __align__(16) float g_QK1[(size_t)NTOK * 128];
__device__ __align__(16) float g_QK2[(size_t)NTOK * 128];
__device__ __align__(16) float g_VT1[(size_t)CDIM * NTOK];   // V^T
__device__ __align__(16) float g_VT2[(size_t)CDIM * NTOK];   // V^T
__device__ __align__(16) float g_Wqk[(size_t)CDIM * 128];
__device__ __align__(16) float g_part[(size_t)2 * 64 * NTOK];
__device__ __align__(16) float g_rinv[2 * NTOK];

// ---------------- helpers ----------------------------------------------------
__device__ __forceinline__ uint32_t f2tf32(float x) {
    uint32_t r;
    asm("cvt.rna.tf32.f32 %0, %1;" : "=r"(r) : "f"(x));
    return r;
}
__device__ __forceinline__ float tf32_round(float x) { return __uint_as_float(f2tf32(x)); }

// truncate-to-tf32 split: hi = 1 LOP3 (alu), lo = 1 FADD (fma pipe)
__device__ __forceinline__ uint32_t tf32_hi(float x) {
    return __float_as_uint(x) & 0xFFFFE000u;
}

__device__ __forceinline__ void mma8(float* c, const uint32_t* a, const uint32_t* b) {
    asm volatile(
        "mma.sync.aligned.m16n8k8.row.col.f32.tf32.tf32.f32 "
        "{%0,%1,%2,%3}, {%4,%5,%6,%7}, {%8,%9}, {%0,%1,%2,%3};"
        : "+f"(c[0]), "+f"(c[1]), "+f"(c[2]), "+f"(c[3])
        : "r"(a[0]), "r"(a[1]), "r"(a[2]), "r"(a[3]), "r"(b[0]), "r"(b[1]));
}

__device__ __forceinline__ uint32_t s2u(const void* p) {
    return (uint32_t)__cvta_generic_to_shared(p);
}
__device__ __forceinline__ void cp16(uint32_t dst, const void* src) {
    asm volatile("cp.async.cg.shared.global [%0], [%1], 16;" :: "r"(dst), "l"(src) : "memory");
}

__global__ void pack_wqk(const float* __restrict__ Wq, const float* __restrict__ Wk,
                         float* __restrict__ Wqk) {
    const int i = blockIdx.x * 256 + threadIdx.x;   // 512*128
    const int r = i >> 7, c = i & 127;
    Wqk[i] = (c < 64) ? Wq[r * 64 + c] : Wk[r * 64 + (c - 64)];
}

// ================= 3xTF32 error-compensated GEMM =============================
// 256 threads, block 128x128, warp tile 64x32. z batches two problems.
// TRB=true : B row-major [K x N] (transposed into smem)  -- projections
// TRB=false: B row-major [N x K]                          -- logits (Q @ K^T)
// EXPSUM   : epilogue writes tf32(exp(acc)) and per-row partial sums to part.
template<bool TRB, bool EXPSUM>
__global__ __launch_bounds__(256, 2)
void gemm3x(const float* __restrict__ A0, const float* __restrict__ A1, int lda,
            const float* __restrict__ B0, const float* __restrict__ B1, int ldb,
            float* __restrict__ C0, float* __restrict__ C1, int ldc, int K,
            float* __restrict__ part)
{
    constexpr int BK = 16, STR = BK + 8;
    __shared__ float As[2][128][STR];
    __shared__ float Bs[2][128][STR];

    const int z = blockIdx.z;
    const float* A = z ? A1 : A0;
    const float* B = z ? B1 : B0;
    float*       C = z ? C1 : C0;

    const int tid  = threadIdx.x;
    const int lane = tid & 31;
    const int wid  = tid >> 5;
    const int wm0  = (wid & 1) << 6;
    const int wn0  = (wid >> 1) << 5;
    const int lr   = lane >> 2;
    const int lc2  = (lane & 3) << 1;

    const size_t row0 = (size_t)blockIdx.y * 128;
    const size_t col0 = (size_t)blockIdx.x * 128;

    const int ar = tid >> 2;
    const int ac = (tid & 3) << 2;
    const float* Ap0 = A + (row0 + ar) * (size_t)lda + ac;
    const float* Ap1 = Ap0 + (size_t)64 * lda;

    const float *Bp0, *Bp1;
    int bk_ = 0, bg4 = 0;
    if (TRB) {
        bk_ = tid & 15;
        bg4 = (tid >> 4) << 2;
        Bp0 = B + (size_t)bk_ * ldb + col0 + bg4;
        Bp1 = Bp0 + 64;
    } else {
        Bp0 = B + (col0 + ar) * (size_t)ldb + ac;
        Bp1 = Bp0 + (size_t)64 * ldb;
    }

    float4 a0 = *(const float4*)Ap0;
    float4 a1 = *(const float4*)Ap1;
    float4 b0 = *(const float4*)Bp0;
    float4 b1 = *(const float4*)Bp1;

    float acc[4][4][4];
#pragma unroll
    for (int i = 0; i < 4; i++)
#pragma unroll
        for (int j = 0; j < 4; j++)
#pragma unroll
            for (int k = 0; k < 4; k++) acc[i][j][k] = 0.f;

    auto store_tiles = [&](int bf, float4 sa0, float4 sa1, float4 sb0, float4 sb1) {
        *(float4*)&As[bf][ar][ac]      = sa0;
        *(float4*)&As[bf][ar + 64][ac] = sa1;
        if (TRB) {
            Bs[bf][bg4 + 0][bk_] = sb0.x;
            Bs[bf][bg4 + 1][bk_] = sb0.y;
            Bs[bf][bg4 + 2][bk_] = sb0.z;
            Bs[bf][bg4 + 3][bk_] = sb0.w;
            Bs[bf][bg4 + 64][bk_] = sb1.x;
            Bs[bf][bg4 + 65][bk_] = sb1.y;
            Bs[bf][bg4 + 66][bk_] = sb1.z;
            Bs[bf][bg4 + 67][bk_] = sb1.w;
        } else {
            *(float4*)&Bs[bf][ar][ac]      = sb0;
            *(float4*)&Bs[bf][ar + 64][ac] = sb1;
        }
    };

    auto compute = [&](int bf) {
#pragma unroll
        for (int kk = 0; kk < BK; kk += 8) {
            uint32_t ah[4][4], al[4][4], bh[4][2], bl[4][2];
#pragma unroll
            for (int mt = 0; mt < 4; mt++) {
                const float2 t0 = *(const float2*)&As[bf][wm0 + mt * 16 + lr][kk + lc2];
                const float2 t1 = *(const float2*)&As[bf][wm0 + mt * 16 + lr + 8][kk + lc2];
                ah[mt][0] = tf32_hi(t0.x); al[mt][0] = __float_as_uint(t0.x - __uint_as_float(ah[mt][0]));
                ah[mt][2] = tf32_hi(t0.y); al[mt][2] = __float_as_uint(t0.y - __uint_as_float(ah[mt][2]));
                ah[mt][1] = tf32_hi(t1.x); al[mt][1] = __float_as_uint(t1.x - __uint_as_float(ah[mt][1]));
                ah[mt][3] = tf32_hi(t1.y); al[mt][3] = __float_as_uint(t1.y - __uint_as_float(ah[mt][3]));
            }
#pragma unroll
            for (int nt = 0; nt < 4; nt++) {
                const float2 t = *(const float2*)&Bs[bf][wn0 + nt * 8 + lr][kk + lc2];
                bh[nt][0] = tf32_hi(t.x); bl[nt][0] = __float_as_uint(t.x - __uint_as_float(bh[nt][0]));
                bh[nt][1] = tf32_hi(t.y); bl[nt][1] = __float_as_uint(t.y - __uint_as_float(bh[nt][1]));
            }
#pragma unroll
            for (int mt = 0; mt < 4; mt++)
#pragma unroll
                for (int nt = 0; nt < 4; nt++) {
                    mma8(acc[mt][nt], ah[mt], bh[nt]);
                    mma8(acc[mt][nt], al[mt], bh[nt]);
                    mma8(acc[mt][nt], ah[mt], bl[nt]);
                }
        }
    };

    store_tiles(0, a0, a1, b0, b1);
    __syncthreads();

    const int KT = K / BK;
    int buf = 0;
    for (int t = 1; t <= KT; t++) {
        if (t < KT) {
            const int ko = t * BK;
            a0 = *(const float4*)(Ap0 + ko);
            a1 = *(const float4*)(Ap1 + ko);
            if (TRB) {
                b0 = *(const float4*)(Bp0 + (size_t)ko * ldb);
                b1 = *(const float4*)(Bp1 + (size_t)ko * ldb);
            } else {
                b0 = *(const float4*)(Bp0 + ko);
                b1 = *(const float4*)(Bp1 + ko);
            }
        }
        compute(buf);
        if (t < KT) {
            buf ^= 1;
            store_tiles(buf, a0, a1, b0, b1);
            __syncthreads();
        }
    }

    if (EXPSUM) {
        __syncthreads();                 // smem reads done; reuse As as scratch
        float* red = &As[0][0][0];
#pragma unroll
        for (int mt = 0; mt < 4; mt++) {
#pragma unroll
            for (int h = 0; h < 2; h++) {
                const int rl = wm0 + mt * 16 + lr + 8 * h;
                float* Crow = C + (row0 + rl) * (size_t)ldc + col0;
                float es = 0.f;
#pragma unroll
                for (int nt = 0; nt < 4; nt++) {
                    const int cc = wn0 + nt * 8 + lc2;
                    float2 v;
                    v.x = tf32_round(__expf(acc[mt][nt][h * 2 + 0]));
                    v.y = tf32_round(__expf(acc[mt][nt][h * 2 + 1]));
                    es += v.x + v.y;
                    *(float2*)(Crow + cc) = v;
                }
                es += __shfl_xor_sync(0xffffffffu, es, 1);
                es += __shfl_xor_sync(0xffffffffu, es, 2);
                if ((lane & 3) == 0) red[(wid >> 1) * 128 + rl] = es;
            }
        }
        __syncthreads();
        if (tid < 128) {
            const float s = red[tid] + red[128 + tid] + red[256 + tid] + red[384 + tid];
            part[((size_t)z * 64 + blockIdx.x) * NTOK + row0 + tid] = s;
        }
    } else {
#pragma unroll
        for (int mt = 0; mt < 4; mt++) {
#pragma unroll
            for (int h = 0; h < 2; h++) {
                const size_t r = row0 + wm0 + mt * 16 + lr + h * 8;
                float* Crow = C + r * (size_t)ldc + col0;
#pragma unroll
                for (int nt = 0; nt < 4; nt++) {
                    const int cc = wn0 + nt * 8 + lc2;
                    float2 v;
                    v.x = acc[mt][nt][h * 2 + 0];
                    v.y = acc[mt][nt][h * 2 + 1];
                    *(float2*)(Crow + cc) = v;
                }
            }
        }
    }
}

__global__ void reduce_rinv(const float* __restrict__ part, float* __restrict__ rinv) {
    const int i = blockIdx.x * 256 + threadIdx.x;   // 0..16383
    const int z = i >> 13, r = i & (NTOK - 1);
    const float* p = part + (size_t)z * 64 * NTOK + r;
    float s = 0.f;
#pragma unroll
    for (int b = 0; b < 64; b++) s += p[(size_t)b * NTOK];
    rinv[i] = 1.f / s;
}

// ================= V projection -> V^T (coalesced via smem transpose) =======
// 128 threads, block 128x128 of V, warp tile 64x64, transposed-B smem.
// Epilogue stages 64x128 transposed tiles in smem (row stride 132 -> 16B
// aligned float4 rows) and writes V^T rows coalesced.
__global__ __launch_bounds__(128, 2)
void vproj_gemm(const float* __restrict__ A0, const float* __restrict__ A1,
                const float* __restrict__ B,
                float* __restrict__ VT0, float* __restrict__ VT1)
{
    constexpr int STR = 24;
    constexpr int TSTR = 132;                                    // mult of 4 -> aligned
    __shared__ __align__(16) float smem_raw[2 * 2 * 128 * STR];  // 49152 B
    float (*As)[128][STR] = (float (*)[128][STR])smem_raw;
    float (*Bs)[128][STR] = (float (*)[128][STR])(smem_raw + 2 * 128 * STR);
    float (*TT)[TSTR]     = (float (*)[TSTR])smem_raw;           // 64x132 = 33792 B

    const int z = blockIdx.z;
    const float* A = z ? A1 : A0;
    float*      VT = z ? VT1 : VT0;

    const int tid  = threadIdx.x;
    const int lane = tid & 31;
    const int wid  = tid >> 5;
    const int wm0  = (wid & 1) << 6;
    const int wn0  = (wid >> 1) << 6;
    const int lr   = lane >> 2;
    const int lc2  = (lane & 3) << 1;

    const size_t row0 = (size_t)blockIdx.y * 128;
    const size_t col0 = (size_t)blockIdx.x * 128;

    const int arr = tid >> 2;
    const int ac4 = (tid & 3) << 2;
    const float* Apb = A + (row0 + arr) * (size_t)CDIM + ac4;
    const size_t astr = (size_t)32 * CDIM;

    const int bk  = tid & 15;
    const int bn0 = (tid >> 4) << 4;
    const float* Bpb = B + (size_t)bk * CDIM + col0 + bn0;

    float acc[4][8][4];
#pragma unroll
    for (int i = 0; i < 4; i++)
#pragma unroll
        for (int j = 0; j < 8; j++)
#pragma unroll
            for (int k = 0; k < 4; k++) acc[i][j][k] = 0.f;

    auto stage = [&](int bf, const float4* av, const float4* bv) {
#pragma unroll
        for (int j = 0; j < 4; j++) {
            float4 v = av[j];
            v.x = tf32_round(v.x); v.y = tf32_round(v.y);
            v.z = tf32_round(v.z); v.w = tf32_round(v.w);
            *(float4*)&As[bf][arr + 32 * j][ac4] = v;
        }
#pragma unroll
        for (int i = 0; i < 4; i++) {
            float4 v = bv[i];
            v.x = tf32_round(v.x); v.y = tf32_round(v.y);
            v.z = tf32_round(v.z); v.w = tf32_round(v.w);
            const int nb = bn0 + 4 * i;
            Bs[bf][nb + 0][bk] = v.x;
            Bs[bf][nb + 1][bk] = v.y;
            Bs[bf][nb + 2][bk] = v.z;
            Bs[bf][nb + 3][bk] = v.w;
        }
    };

    float4 av[4], bv[4];
#pragma unroll
    for (int j = 0; j < 4; j++) av[j] = *(const float4*)(Apb + j * astr);
#pragma unroll
    for (int i = 0; i < 4; i++) bv[i] = *(const float4*)(Bpb + 4 * i);
    stage(0, av, bv);
    __syncthreads();

    const int KT = CDIM / 16;
    int buf = 0;
    for (int t = 1; t <= KT; t++) {
        if (t < KT) {
            const size_t ko = (size_t)t * 16;
#pragma unroll
            for (int j = 0; j < 4; j++) av[j] = *(const float4*)(Apb + j * astr + ko);
#pragma unroll
            for (int i = 0; i < 4; i++) bv[i] = *(const float4*)(Bpb + ko * CDIM + 4 * i);
        }
#pragma unroll
        for (int kk = 0; kk < 16; kk += 8) {
            uint32_t ah[4][4], bh[8][2];
#pragma unroll
            for (int mt = 0; mt < 4; mt++) {
                const float2 t0 = *(const float2*)&As[buf][wm0 + mt * 16 + lr][kk + lc2];
                const float2 t1 = *(const float2*)&As[buf][wm0 + mt * 16 + lr + 8][kk + lc2];
                ah[mt][0] = __float_as_uint(t0.x);
                ah[mt][1] = __float_as_uint(t1.x);
                ah[mt][2] = __float_as_uint(t0.y);
                ah[mt][3] = __float_as_uint(t1.y);
            }
#pragma unroll
            for (int nt = 0; nt < 8; nt++) {
                const float2 t = *(const float2*)&Bs[buf][wn0 + nt * 8 + lr][kk + lc2];
                bh[nt][0] = __float_as_uint(t.x);
                bh[nt][1] = __float_as_uint(t.y);
            }
#pragma unroll
            for (int mt = 0; mt < 4; mt++)
#pragma unroll
                for (int nt = 0; nt < 8; nt++)
                    mma8(acc[mt][nt], ah[mt], bh[nt]);
        }
        if (t < KT) {
            buf ^= 1;
            stage(buf, av, bv);
            __syncthreads();
        }
    }

    // transposed epilogue via smem: two 64-col halves
    __syncthreads();   // all warps done reading As/Bs before aliasing as TT
#pragma unroll
    for (int half = 0; half < 2; half++) {
        if ((wid >> 1) == half) {          // warps owning cols [64*half, 64*half+64)
#pragma unroll
            for (int mt = 0; mt < 4; mt++)
#pragma unroll
                for (int h = 0; h < 2; h++) {
                    const int rl = wm0 + mt * 16 + lr + h * 8;
#pragma unroll
                    for (int nt = 0; nt < 8; nt++) {
                        const int cl = nt * 8 + lc2;     // 0..63 within half
                        TT[cl][rl]     = tf32_round(acc[mt][nt][h * 2 + 0]);
                        TT[cl + 1][rl] = tf32_round(acc[mt][nt][h * 2 + 1]);
                    }
                }
        }
        __syncthreads();
        {
            const int c2 = tid >> 1;                 // 0..63
            const int po = (tid & 1) << 6;           // 0,64
            const size_t gc = col0 + 64 * half + c2;
            float* dst = VT + gc * (size_t)NTOK + row0 + po;
            const float* src = &TT[c2][po];          // 16B aligned (TSTR mult of 4)
#pragma unroll
            for (int i = 0; i < 16; i++)
                *(float4*)(dst + 4 * i) = *(const float4*)(src + 4 * i);
        }
        __syncthreads();
    }
}

// ================= PV GEMM: 128x256 tile, cp.async 3-stage, 1 sync/iter =====
// A = S [NTOK x NTOK] (rows k-contig), B = V^T [CDIM x NTOK] (rows k-contig).
// Epilogue: C = acc * rinv[row] + Res.
#define PV_STAGES 3
__global__ __launch_bounds__(256, 1)
void pv_gemm(const float* __restrict__ A0, const float* __restrict__ A1,
             const float* __restrict__ BT0, const float* __restrict__ BT1,
             const float* __restrict__ R0, const float* __restrict__ R1,
             float* __restrict__ C0, float* __restrict__ C1,
             const float* __restrict__ RI)
{
    constexpr int STR = 24;
    extern __shared__ float dsm[];
    float (*As)[128][STR] = (float (*)[128][STR])dsm;                        // [3][128][24]
    float (*Bs)[256][STR] = (float (*)[256][STR])(dsm + PV_STAGES * 128 * STR);

    const int z = blockIdx.z;
    const float* A   = z ? A1 : A0;
    const float* BT  = z ? BT1 : BT0;
    const float* Res = z ? R1 : R0;
    float*       C   = z ? C1 : C0;

    const int tid  = threadIdx.x;
    const int lane = tid & 31;
    const int wid  = tid >> 5;          // 0..7
    const int wm0  = (wid & 1) << 6;    // 0,64
    const int wn0  = (wid >> 1) << 6;   // 0,64,128,192
    const int lr   = lane >> 2;
    const int lc2  = (lane & 3) << 1;

    const size_t row0 = (size_t)blockIdx.y * 128;
    const size_t col0 = (size_t)blockIdx.x * 256;

    const int arr = tid >> 1;
    const int ac8 = (tid & 1) << 3;
    const float* Apb = A + (row0 + arr) * (size_t)NTOK + ac8;
    const float* Bpb = BT + (col0 + tid) * (size_t)NTOK;

    float acc[4][8][4];
#pragma unroll
    for (int i = 0; i < 4; i++)
#pragma unroll
        for (int j = 0; j < 8; j++)
#pragma unroll
            for (int k = 0; k < 4; k++) acc[i][j][k] = 0.f;

    auto issue = [&](int t) {
        const int bf = t % PV_STAGES;
        const float* a = Apb + (size_t)t * 16;
        const uint32_t da = s2u(&As[bf][arr][ac8]);
        cp16(da, a);
        cp16(da + 16, a + 4);
        const float* b = Bpb + (size_t)t * 16;
        const uint32_t db = s2u(&Bs[bf][tid][0]);
        cp16(db, b);
        cp16(db + 16, b + 4);
        cp16(db + 32, b + 8);
        cp16(db + 48, b + 12);
        asm volatile("cp.async.commit_group;" ::: "memory");
    };

    // double-buffered fragments: both k8 groups loaded before MMAs
    uint32_t ah[2][4][4], bh[2][8][2];
    auto ldfrag = [&](int buf, int kk, int f) {
#pragma unroll
        for (int mt = 0; mt < 4; mt++) {
            const float2 t0 = *(const float2*)&As[buf][wm0 + mt * 16 + lr][kk + lc2];
            const float2 t1 = *(const float2*)&As[buf][wm0 + mt * 16 + lr + 8][kk + lc2];
            ah[f][mt][0] = __float_as_uint(t0.x);
            ah[f][mt][1] = __float_as_uint(t1.x);
            ah[f][mt][2] = __float_as_uint(t0.y);
            ah[f][mt][3] = __float_as_uint(t1.y);
        }
#pragma unroll
        for (int nt = 0; nt < 8; nt++) {
            const float2 t2 = *(const float2*)&Bs[buf][wn0 + nt * 8 + lr][kk + lc2];
            bh[f][nt][0] = __float_as_uint(t2.x);
            bh[f][nt][1] = __float_as_uint(t2.y);
        }
    };

    const int KT = NTOK / 16;           // 512
    issue(0);
    issue(1);

    for (int t = 0; t < KT; t++) {
        if (t + 1 < KT) {
            asm volatile("cp.async.wait_group 1;" ::: "memory");
        } else {
            asm volatile("cp.async.wait_group 0;" ::: "memory");
        }
        __syncthreads();
        if (t + 2 < KT) issue(t + 2);   // safe: stage (t+2)%3 last read in compute(t-1)

        const int buf = t % PV_STAGES;
        ldfrag(buf, 0, 0);
        ldfrag(buf, 8, 1);
#pragma unroll
        for (int f = 0; f < 2; f++)
#pragma unroll
            for (int mt = 0; mt < 4; mt++)
#pragma unroll
                for (int nt = 0; nt < 8; nt++)
                    mma8(acc[mt][nt], ah[f][mt], bh[f][nt]);
    }

    // epilogue: scale by rinv, add residual
#pragma unroll
    for (int mt = 0; mt < 4; mt++) {
#pragma unroll
        for (int h = 0; h < 2; h++) {
            const size_t r = row0 + wm0 + mt * 16 + lr + h * 8;
            const float scale = RI[(size_t)z * NTOK + r];
            float* Crow = C + r * (size_t)CDIM + col0;
            const float* Rrow = Res + r * (size_t)CDIM + col0;
#pragma unroll
            for (int nt = 0; nt < 8; nt++) {
                const int cc = wn0 + nt * 8 + lc2;
                const float2 rv = *(const float2*)(Rrow + cc);
                float2 v;
                v.x = acc[mt][nt][h * 2 + 0] * scale + rv.x;
                v.y = acc[mt][nt][h * 2 + 1] * scale + rv.y;
                *(float2*)(Crow + cc) = v;
            }
        }
    }
}

// ---------------- launch -----------------------------------------------------
extern "C" void kernel_launch(void* const* d_in, const int* in_sizes, int n_in,
                              void* d_out, int out_size)
{
    const float* im1 = (const float*)d_in[0];
    const float* im2 = (const float*)d_in[1];
    const float* Wq  = (const float*)d_in[2];
    const float* Wk  = (const float*)d_in[3];
    const float* Wv  = (const float*)d_in[4];

    float* out1 = (float*)d_out;
    float* out2 = out1 + (size_t)NTOK * CDIM;

    float *pS1, *pS2, *pQK1, *pQK2, *pVT1, *pVT2, *pWqk, *pPart, *pRinv;
    cudaGetSymbolAddress((void**)&pS1,   g_S1);
    cudaGetSymbolAddress((void**)&pS2,   g_S2);
    cudaGetSymbolAddress((void**)&pQK1,  g_QK1);
    cudaGetSymbolAddress((void**)&pQK2,  g_QK2);
    cudaGetSymbolAddress((void**)&pVT1,  g_VT1);
    cudaGetSymbolAddress((void**)&pVT2,  g_VT2);
    cudaGetSymbolAddress((void**)&pWqk,  g_Wqk);
    cudaGetSymbolAddress((void**)&pPart, g_part);
    cudaGetSymbolAddress((void**)&pRinv, g_rinv);

    const int PV_SMEM = PV_STAGES * (128 * 24 + 256 * 24) * 4;   // 110592 B
    static bool attr_set = false;
    if (!attr_set) {
        cudaFuncSetAttribute(pv_gemm, cudaFuncAttributeMaxDynamicSharedMemorySize, PV_SMEM);
        attr_set = true;
    }

    pack_wqk<<<256, 256>>>(Wq, Wk, pWqk);

    // Q/K projections (3xTF32, near-fp32): [Q|K]z = imz @ [Wq|Wk]
    gemm3x<true, false><<<dim3(1, 64, 2), 256>>>(im1, im2, CDIM, pWqk, pWqk, 128,
                                                 pQK1, pQK2, 128, CDIM, nullptr);
    // V projections -> V^T (single-pass tf32, coalesced transpose epilogue)
    vproj_gemm<<<dim3(4, 64, 2), 128>>>(im1, im2, Wv, pVT1, pVT2);
    // logits + fused exp + partial row sums: S1 = exp(Q2 K1^T), S2 = exp(Q1 K2^T)
    gemm3x<false, true><<<dim3(64, 64, 2), 256>>>(pQK2, pQK1, 128, pQK1 + 64, pQK2 + 64, 128,
                                                  pS1, pS2, NTOK, 64, pPart);
    reduce_rinv<<<64, 256>>>(pPart, pRinv);
    // PV: out = (S @ V) * rinv + im   (cp.async 3-stage, 1 sync/iter, frag DB)
    pv_gemm<<<dim3(2, 64, 2), 256, PV_SMEM>>>(pS1, pS2, pVT1, pVT2,
                                              im1, im2, out1, out2, pRinv);
}

// round 11
// speedup vs baseline: 1.1845x; 1.1711x over previous
#include <cuda_runtime.h>
#include <cstdint>
#include <cstddef>

#define NTOK 8192
#define CDIM 512

// ---------------- scratch (device globals; no allocations allowed) ----------
__device__ __align__(16) float g_S1[(size_t)NTOK * NTOK];
__device__ __align__(16) float g_S2[(size_t)NTOK * NTOK];
__device__ __align__(16) float g_QK1[(size_t)NTOK * 128];
__device__ __align__(16) float g_QK2[(size_t)NTOK * 128];
__device__ __align__(16) float g_VT1[(size_t)CDIM * NTOK];   // V^T
__device__ __align__(16) float g_VT2[(size_t)CDIM * NTOK];   // V^T
__device__ __align__(16) float g_Wqk[(size_t)CDIM * 128];
__device__ __align__(16) float g_part[(size_t)2 * 64 * NTOK];
__device__ __align__(16) float g_rinv[2 * NTOK];

// ---------------- helpers ----------------------------------------------------
__device__ __forceinline__ uint32_t f2tf32(float x) {
    uint32_t r;
    asm("cvt.rna.tf32.f32 %0, %1;" : "=r"(r) : "f"(x));
    return r;
}
__device__ __forceinline__ float tf32_round(float x) { return __uint_as_float(f2tf32(x)); }

// truncate-to-tf32 split: hi = 1 LOP3 (alu), lo = 1 FADD (fma pipe)
__device__ __forceinline__ uint32_t tf32_hi(float x) {
    return __float_as_uint(x) & 0xFFFFE000u;
}

__device__ __forceinline__ void mma8(float* c, const uint32_t* a, const uint32_t* b) {
    asm volatile(
        "mma.sync.aligned.m16n8k8.row.col.f32.tf32.tf32.f32 "
        "{%0,%1,%2,%3}, {%4,%5,%6,%7}, {%8,%9}, {%0,%1,%2,%3};"
        : "+f"(c[0]), "+f"(c[1]), "+f"(c[2]), "+f"(c[3])
        : "r"(a[0]), "r"(a[1]), "r"(a[2]), "r"(a[3]), "r"(b[0]), "r"(b[1]));
}

__global__ void pack_wqk(const float* __restrict__ Wq, const float* __restrict__ Wk,
                         float* __restrict__ Wqk) {
    const int i = blockIdx.x * 256 + threadIdx.x;   // 512*128
    const int r = i >> 7, c = i & 127;
    Wqk[i] = (c < 64) ? Wq[r * 64 + c] : Wk[r * 64 + (c - 64)];
}

// ================= 3xTF32 error-compensated GEMM =============================
// 256 threads, block 128x128, warp tile 64x32. z batches two problems.
// TRB=true : B row-major [K x N] (transposed into smem)  -- projections
// TRB=false: B row-major [N x K]                          -- logits (Q @ K^T)
// EXPSUM   : epilogue writes tf32(exp(acc)) and per-row partial sums to part.
template<bool TRB, bool EXPSUM>
__global__ __launch_bounds__(256, 2)
void gemm3x(const float* __restrict__ A0, const float* __restrict__ A1, int lda,
            const float* __restrict__ B0, const float* __restrict__ B1, int ldb,
            float* __restrict__ C0, float* __restrict__ C1, int ldc, int K,
            float* __restrict__ part)
{
    constexpr int BK = 16, STR = BK + 8;
    __shared__ float As[2][128][STR];
    __shared__ float Bs[2][128][STR];

    const int z = blockIdx.z;
    const float* A = z ? A1 : A0;
    const float* B = z ? B1 : B0;
    float*       C = z ? C1 : C0;

    const int tid  = threadIdx.x;
    const int lane = tid & 31;
    const int wid  = tid >> 5;
    const int wm0  = (wid & 1) << 6;
    const int wn0  = (wid >> 1) << 5;
    const int lr   = lane >> 2;
    const int lc2  = (lane & 3) << 1;

    const size_t row0 = (size_t)blockIdx.y * 128;
    const size_t col0 = (size_t)blockIdx.x * 128;

    const int ar = tid >> 2;
    const int ac = (tid & 3) << 2;
    const float* Ap0 = A + (row0 + ar) * (size_t)lda + ac;
    const float* Ap1 = Ap0 + (size_t)64 * lda;

    const float *Bp0, *Bp1;
    int bk_ = 0, bg4 = 0;
    if (TRB) {
        bk_ = tid & 15;
        bg4 = (tid >> 4) << 2;
        Bp0 = B + (size_t)bk_ * ldb + col0 + bg4;
        Bp1 = Bp0 + 64;
    } else {
        Bp0 = B + (col0 + ar) * (size_t)ldb + ac;
        Bp1 = Bp0 + (size_t)64 * ldb;
    }

    float4 a0 = *(const float4*)Ap0;
    float4 a1 = *(const float4*)Ap1;
    float4 b0 = *(const float4*)Bp0;
    float4 b1 = *(const float4*)Bp1;

    float acc[4][4][4];
#pragma unroll
    for (int i = 0; i < 4; i++)
#pragma unroll
        for (int j = 0; j < 4; j++)
#pragma unroll
            for (int k = 0; k < 4; k++) acc[i][j][k] = 0.f;

    auto store_tiles = [&](int bf, float4 sa0, float4 sa1, float4 sb0, float4 sb1) {
        *(float4*)&As[bf][ar][ac]      = sa0;
        *(float4*)&As[bf][ar + 64][ac] = sa1;
        if (TRB) {
            Bs[bf][bg4 + 0][bk_] = sb0.x;
            Bs[bf][bg4 + 1][bk_] = sb0.y;
            Bs[bf][bg4 + 2][bk_] = sb0.z;
            Bs[bf][bg4 + 3][bk_] = sb0.w;
            Bs[bf][bg4 + 64][bk_] = sb1.x;
            Bs[bf][bg4 + 65][bk_] = sb1.y;
            Bs[bf][bg4 + 66][bk_] = sb1.z;
            Bs[bf][bg4 + 67][bk_] = sb1.w;
        } else {
            *(float4*)&Bs[bf][ar][ac]      = sb0;
            *(float4*)&Bs[bf][ar + 64][ac] = sb1;
        }
    };

    auto compute = [&](int bf) {
#pragma unroll
        for (int kk = 0; kk < BK; kk += 8) {
            uint32_t ah[4][4], al[4][4], bh[4][2], bl[4][2];
#pragma unroll
            for (int mt = 0; mt < 4; mt++) {
                const float2 t0 = *(const float2*)&As[bf][wm0 + mt * 16 + lr][kk + lc2];
                const float2 t1 = *(const float2*)&As[bf][wm0 + mt * 16 + lr + 8][kk + lc2];
                ah[mt][0] = tf32_hi(t0.x); al[mt][0] = __float_as_uint(t0.x - __uint_as_float(ah[mt][0]));
                ah[mt][2] = tf32_hi(t0.y); al[mt][2] = __float_as_uint(t0.y - __uint_as_float(ah[mt][2]));
                ah[mt][1] = tf32_hi(t1.x); al[mt][1] = __float_as_uint(t1.x - __uint_as_float(ah[mt][1]));
                ah[mt][3] = tf32_hi(t1.y); al[mt][3] = __float_as_uint(t1.y - __uint_as_float(ah[mt][3]));
            }
#pragma unroll
            for (int nt = 0; nt < 4; nt++) {
                const float2 t = *(const float2*)&Bs[bf][wn0 + nt * 8 + lr][kk + lc2];
                bh[nt][0] = tf32_hi(t.x); bl[nt][0] = __float_as_uint(t.x - __uint_as_float(bh[nt][0]));
                bh[nt][1] = tf32_hi(t.y); bl[nt][1] = __float_as_uint(t.y - __uint_as_float(bh[nt][1]));
            }
#pragma unroll
            for (int mt = 0; mt < 4; mt++)
#pragma unroll
                for (int nt = 0; nt < 4; nt++) {
                    mma8(acc[mt][nt], ah[mt], bh[nt]);
                    mma8(acc[mt][nt], al[mt], bh[nt]);
                    mma8(acc[mt][nt], ah[mt], bl[nt]);
                }
        }
    };

    store_tiles(0, a0, a1, b0, b1);
    __syncthreads();

    const int KT = K / BK;
    int buf = 0;
    for (int t = 1; t <= KT; t++) {
        if (t < KT) {
            const int ko = t * BK;
            a0 = *(const float4*)(Ap0 + ko);
            a1 = *(const float4*)(Ap1 + ko);
            if (TRB) {
                b0 = *(const float4*)(Bp0 + (size_t)ko * ldb);
                b1 = *(const float4*)(Bp1 + (size_t)ko * ldb);
            } else {
                b0 = *(const float4*)(Bp0 + ko);
                b1 = *(const float4*)(Bp1 + ko);
            }
        }
        compute(buf);
        if (t < KT) {
            buf ^= 1;
            store_tiles(buf, a0, a1, b0, b1);
            __syncthreads();
        }
    }

    if (EXPSUM) {
        __syncthreads();                 // smem reads done; reuse As as scratch
        float* red = &As[0][0][0];
#pragma unroll
        for (int mt = 0; mt < 4; mt++) {
#pragma unroll
            for (int h = 0; h < 2; h++) {
                const int rl = wm0 + mt * 16 + lr + 8 * h;
                float* Crow = C + (row0 + rl) * (size_t)ldc + col0;
                float es = 0.f;
#pragma unroll
                for (int nt = 0; nt < 4; nt++) {
                    const int cc = wn0 + nt * 8 + lc2;
                    float2 v;
                    v.x = tf32_round(__expf(acc[mt][nt][h * 2 + 0]));
                    v.y = tf32_round(__expf(acc[mt][nt][h * 2 + 1]));
                    es += v.x + v.y;
                    *(float2*)(Crow + cc) = v;
                }
                es += __shfl_xor_sync(0xffffffffu, es, 1);
                es += __shfl_xor_sync(0xffffffffu, es, 2);
                if ((lane & 3) == 0) red[(wid >> 1) * 128 + rl] = es;
            }
        }
        __syncthreads();
        if (tid < 128) {
            const float s = red[tid] + red[128 + tid] + red[256 + tid] + red[384 + tid];
            part[((size_t)z * 64 + blockIdx.x) * NTOK + row0 + tid] = s;
        }
    } else {
#pragma unroll
        for (int mt = 0; mt < 4; mt++) {
#pragma unroll
            for (int h = 0; h < 2; h++) {
                const size_t r = row0 + wm0 + mt * 16 + lr + h * 8;
                float* Crow = C + r * (size_t)ldc + col0;
#pragma unroll
                for (int nt = 0; nt < 4; nt++) {
                    const int cc = wn0 + nt * 8 + lc2;
                    float2 v;
                    v.x = acc[mt][nt][h * 2 + 0];
                    v.y = acc[mt][nt][h * 2 + 1];
                    *(float2*)(Crow + cc) = v;
                }
            }
        }
    }
}

__global__ void reduce_rinv(const float* __restrict__ part, float* __restrict__ rinv) {
    const int i = blockIdx.x * 256 + threadIdx.x;   // 0..16383
    const int z = i >> 13, r = i & (NTOK - 1);
    const float* p = part + (size_t)z * 64 * NTOK + r;
    float s = 0.f;
#pragma unroll
    for (int b = 0; b < 64; b++) s += p[(size_t)b * NTOK];
    rinv[i] = 1.f / s;
}

// ================= V projection -> V^T (coalesced via smem transpose) =======
__global__ __launch_bounds__(128, 2)
void vproj_gemm(const float* __restrict__ A0, const float* __restrict__ A1,
                const float* __restrict__ B,
                float* __restrict__ VT0, float* __restrict__ VT1)
{
    constexpr int STR = 24;
    constexpr int TSTR = 132;                                    // mult of 4 -> aligned
    __shared__ __align__(16) float smem_raw[2 * 2 * 128 * STR];  // 49152 B
    float (*As)[128][STR] = (float (*)[128][STR])smem_raw;
    float (*Bs)[128][STR] = (float (*)[128][STR])(smem_raw + 2 * 128 * STR);
    float (*TT)[TSTR]     = (float (*)[TSTR])smem_raw;           // 64x132 = 33792 B

    const int z = blockIdx.z;
    const float* A = z ? A1 : A0;
    float*      VT = z ? VT1 : VT0;

    const int tid  = threadIdx.x;
    const int lane = tid & 31;
    const int wid  = tid >> 5;
    const int wm0  = (wid & 1) << 6;
    const int wn0  = (wid >> 1) << 6;
    const int lr   = lane >> 2;
    const int lc2  = (lane & 3) << 1;

    const size_t row0 = (size_t)blockIdx.y * 128;
    const size_t col0 = (size_t)blockIdx.x * 128;

    const int arr = tid >> 2;
    const int ac4 = (tid & 3) << 2;
    const float* Apb = A + (row0 + arr) * (size_t)CDIM + ac4;
    const size_t astr = (size_t)32 * CDIM;

    const int bk  = tid & 15;
    const int bn0 = (tid >> 4) << 4;
    const float* Bpb = B + (size_t)bk * CDIM + col0 + bn0;

    float acc[4][8][4];
#pragma unroll
    for (int i = 0; i < 4; i++)
#pragma unroll
        for (int j = 0; j < 8; j++)
#pragma unroll
            for (int k = 0; k < 4; k++) acc[i][j][k] = 0.f;

    auto stage = [&](int bf, const float4* av, const float4* bv) {
#pragma unroll
        for (int j = 0; j < 4; j++) {
            float4 v = av[j];
            v.x = tf32_round(v.x); v.y = tf32_round(v.y);
            v.z = tf32_round(v.z); v.w = tf32_round(v.w);
            *(float4*)&As[bf][arr + 32 * j][ac4] = v;
        }
#pragma unroll
        for (int i = 0; i < 4; i++) {
            float4 v = bv[i];
            v.x = tf32_round(v.x); v.y = tf32_round(v.y);
            v.z = tf32_round(v.z); v.w = tf32_round(v.w);
            const int nb = bn0 + 4 * i;
            Bs[bf][nb + 0][bk] = v.x;
            Bs[bf][nb + 1][bk] = v.y;
            Bs[bf][nb + 2][bk] = v.z;
            Bs[bf][nb + 3][bk] = v.w;
        }
    };

    float4 av[4], bv[4];
#pragma unroll
    for (int j = 0; j < 4; j++) av[j] = *(const float4*)(Apb + j * astr);
#pragma unroll
    for (int i = 0; i < 4; i++) bv[i] = *(const float4*)(Bpb + 4 * i);
    stage(0, av, bv);
    __syncthreads();

    const int KT = CDIM / 16;
    int buf = 0;
    for (int t = 1; t <= KT; t++) {
        if (t < KT) {
            const size_t ko = (size_t)t * 16;
#pragma unroll
            for (int j = 0; j < 4; j++) av[j] = *(const float4*)(Apb + j * astr + ko);
#pragma unroll
            for (int i = 0; i < 4; i++) bv[i] = *(const float4*)(Bpb + ko * CDIM + 4 * i);
        }
#pragma unroll
        for (int kk = 0; kk < 16; kk += 8) {
            uint32_t ah[4][4], bh[8][2];
#pragma unroll
            for (int mt = 0; mt < 4; mt++) {
                const float2 t0 = *(const float2*)&As[buf][wm0 + mt * 16 + lr][kk + lc2];
                const float2 t1 = *(const float2*)&As[buf][wm0 + mt * 16 + lr + 8][kk + lc2];
                ah[mt][0] = __float_as_uint(t0.x);
                ah[mt][1] = __float_as_uint(t1.x);
                ah[mt][2] = __float_as_uint(t0.y);
                ah[mt][3] = __float_as_uint(t1.y);
            }
#pragma unroll
            for (int nt = 0; nt < 8; nt++) {
                const float2 t = *(const float2*)&Bs[buf][wn0 + nt * 8 + lr][kk + lc2];
                bh[nt][0] = __float_as_uint(t.x);
                bh[nt][1] = __float_as_uint(t.y);
            }
#pragma unroll
            for (int mt = 0; mt < 4; mt++)
#pragma unroll
                for (int nt = 0; nt < 8; nt++)
                    mma8(acc[mt][nt], ah[mt], bh[nt]);
        }
        if (t < KT) {
            buf ^= 1;
            stage(buf, av, bv);
            __syncthreads();
        }
    }

    // transposed epilogue via smem: two 64-col halves
    __syncthreads();   // all warps done reading As/Bs before aliasing as TT
#pragma unroll
    for (int half = 0; half < 2; half++) {
        if ((wid >> 1) == half) {          // warps owning cols [64*half, 64*half+64)
#pragma unroll
            for (int mt = 0; mt < 4; mt++)
#pragma unroll
                for (int h = 0; h < 2; h++) {
                    const int rl = wm0 + mt * 16 + lr + h * 8;
#pragma unroll
                    for (int nt = 0; nt < 8; nt++) {
                        const int cl = nt * 8 + lc2;     // 0..63 within half
                        TT[cl][rl]     = tf32_round(acc[mt][nt][h * 2 + 0]);
                        TT[cl + 1][rl] = tf32_round(acc[mt][nt][h * 2 + 1]);
                    }
                }
        }
        __syncthreads();
        {
            const int c2 = tid >> 1;                 // 0..63
            const int po = (tid & 1) << 6;           // 0,64
            const size_t gc = col0 + 64 * half + c2;
            float* dst = VT + gc * (size_t)NTOK + row0 + po;
            const float* src = &TT[c2][po];          // 16B aligned (TSTR mult of 4)
#pragma unroll
            for (int i = 0; i < 16; i++)
                *(float4*)(dst + 4 * i) = *(const float4*)(src + 4 * i);
        }
        __syncthreads();
    }
}

// ================= PV GEMM: gemm3x-shaped single-pass (16 warps/SM) =========
// Exactly the measured-49.5%-tensor configuration: 128x128 tile, 256 threads,
// warp tile 64x32, double-buffered sync staging, occupancy 2.
// A = S [NTOK x NTOK], B = V^T [CDIM x NTOK] (both rows k-contiguous, NT form).
// Epilogue: C = acc * rinv[row] + Res.
__global__ __launch_bounds__(256, 2)
void pv_gemm(const float* __restrict__ A0, const float* __restrict__ A1,
             const float* __restrict__ B0, const float* __restrict__ B1,
             const float* __restrict__ R0, const float* __restrict__ R1,
             float* __restrict__ C0, float* __restrict__ C1,
             const float* __restrict__ RI)
{
    constexpr int BK = 16, STR = BK + 8;
    __shared__ float As[2][128][STR];
    __shared__ float Bs[2][128][STR];

    const int z = blockIdx.z;
    const float* A   = z ? A1 : A0;
    const float* B   = z ? B1 : B0;
    const float* Res = z ? R1 : R0;
    float*       C   = z ? C1 : C0;

    const int tid  = threadIdx.x;
    const int lane = tid & 31;
    const int wid  = tid >> 5;
    const int wm0  = (wid & 1) << 6;
    const int wn0  = (wid >> 1) << 5;
    const int lr   = lane >> 2;
    const int lc2  = (lane & 3) << 1;

    const size_t row0 = (size_t)blockIdx.y * 128;
    const size_t col0 = (size_t)blockIdx.x * 128;

    const int ar = tid >> 2;
    const int ac = (tid & 3) << 2;
    const float* Ap0 = A + (row0 + ar) * (size_t)NTOK + ac;
    const float* Ap1 = Ap0 + (size_t)64 * NTOK;
    const float* Bp0 = B + (col0 + ar) * (size_t)NTOK + ac;
    const float* Bp1 = Bp0 + (size_t)64 * NTOK;

    float4 a0 = *(const float4*)Ap0;
    float4 a1 = *(const float4*)Ap1;
    float4 b0 = *(const float4*)Bp0;
    float4 b1 = *(const float4*)Bp1;

    float acc[4][4][4];
#pragma unroll
    for (int i = 0; i < 4; i++)
#pragma unroll
        for (int j = 0; j < 4; j++)
#pragma unroll
            for (int k = 0; k < 4; k++) acc[i][j][k] = 0.f;

    auto store_tiles = [&](int bf) {
        *(float4*)&As[bf][ar][ac]      = a0;
        *(float4*)&As[bf][ar + 64][ac] = a1;
        *(float4*)&Bs[bf][ar][ac]      = b0;
        *(float4*)&Bs[bf][ar + 64][ac] = b1;
    };

    auto compute = [&](int bf) {
#pragma unroll
        for (int kk = 0; kk < BK; kk += 8) {
            uint32_t ah[4][4], bh[4][2];
#pragma unroll
            for (int mt = 0; mt < 4; mt++) {
                const float2 t0 = *(const float2*)&As[bf][wm0 + mt * 16 + lr][kk + lc2];
                const float2 t1 = *(const float2*)&As[bf][wm0 + mt * 16 + lr + 8][kk + lc2];
                ah[mt][0] = __float_as_uint(t0.x);
                ah[mt][1] = __float_as_uint(t1.x);
                ah[mt][2] = __float_as_uint(t0.y);
                ah[mt][3] = __float_as_uint(t1.y);
            }
#pragma unroll
            for (int nt = 0; nt < 4; nt++) {
                const float2 t = *(const float2*)&Bs[bf][wn0 + nt * 8 + lr][kk + lc2];
                bh[nt][0] = __float_as_uint(t.x);
                bh[nt][1] = __float_as_uint(t.y);
            }
#pragma unroll
            for (int mt = 0; mt < 4; mt++)
#pragma unroll
                for (int nt = 0; nt < 4; nt++)
                    mma8(acc[mt][nt], ah[mt], bh[nt]);
        }
    };

    store_tiles(0);
    __syncthreads();

    const int KT = NTOK / BK;           // 512
    int buf = 0;
    for (int t = 1; t <= KT; t++) {
        if (t < KT) {
            const size_t ko = (size_t)t * BK;
            a0 = *(const float4*)(Ap0 + ko);
            a1 = *(const float4*)(Ap1 + ko);
            b0 = *(const float4*)(Bp0 + ko);
            b1 = *(const float4*)(Bp1 + ko);
        }
        compute(buf);
        if (t < KT) {
            buf ^= 1;
            store_tiles(buf);
            __syncthreads();
        }
    }

    // epilogue: scale by rinv, add residual
#pragma unroll
    for (int mt = 0; mt < 4; mt++) {
#pragma unroll
        for (int h = 0; h < 2; h++) {
            const size_t r = row0 + wm0 + mt * 16 + lr + h * 8;
            const float scale = RI[(size_t)z * NTOK + r];
            float* Crow = C + r * (size_t)CDIM + col0;
            const float* Rrow = Res + r * (size_t)CDIM + col0;
#pragma unroll
            for (int nt = 0; nt < 4; nt++) {
                const int cc = wn0 + nt * 8 + lc2;
                const float2 rv = *(const float2*)(Rrow + cc);
                float2 v;
                v.x = acc[mt][nt][h * 2 + 0] * scale + rv.x;
                v.y = acc[mt][nt][h * 2 + 1] * scale + rv.y;
                *(float2*)(Crow + cc) = v;
            }
        }
    }
}

// ---------------- launch -----------------------------------------------------
extern "C" void kernel_launch(void* const* d_in, const int* in_sizes, int n_in,
                              void* d_out, int out_size)
{
    const float* im1 = (const float*)d_in[0];
    const float* im2 = (const float*)d_in[1];
    const float* Wq  = (const float*)d_in[2];
    const float* Wk  = (const float*)d_in[3];
    const float* Wv  = (const float*)d_in[4];

    float* out1 = (float*)d_out;
    float* out2 = out1 + (size_t)NTOK * CDIM;

    float *pS1, *pS2, *pQK1, *pQK2, *pVT1, *pVT2, *pWqk, *pPart, *pRinv;
    cudaGetSymbolAddress((void**)&pS1,   g_S1);
    cudaGetSymbolAddress((void**)&pS2,   g_S2);
    cudaGetSymbolAddress((void**)&pQK1,  g_QK1);
    cudaGetSymbolAddress((void**)&pQK2,  g_QK2);
    cudaGetSymbolAddress((void**)&pVT1,  g_VT1);
    cudaGetSymbolAddress((void**)&pVT2,  g_VT2);
    cudaGetSymbolAddress((void**)&pWqk,  g_Wqk);
    cudaGetSymbolAddress((void**)&pPart, g_part);
    cudaGetSymbolAddress((void**)&pRinv, g_rinv);

    pack_wqk<<<256, 256>>>(Wq, Wk, pWqk);

    // Q/K projections (3xTF32, near-fp32): [Q|K]z = imz @ [Wq|Wk]
    gemm3x<true, false><<<dim3(1, 64, 2), 256>>>(im1, im2, CDIM, pWqk, pWqk, 128,
                                                 pQK1, pQK2, 128, CDIM, nullptr);
    // V projections -> V^T (single-pass tf32, coalesced transpose epilogue)
    vproj_gemm<<<dim3(4, 64, 2), 128>>>(im1, im2, Wv, pVT1, pVT2);
    // logits + fused exp + partial row sums: S1 = exp(Q2 K1^T), S2 = exp(Q1 K2^T)
    gemm3x<false, true><<<dim3(64, 64, 2), 256>>>(pQK2, pQK1, 128, pQK1 + 64, pQK2 + 64, 128,
                                                  pS1, pS2, NTOK, 64, pPart);
    reduce_rinv<<<64, 256>>>(pPart, pRinv);
    // PV: out = (S @ V) * rinv + im   (gemm3x-shaped, 16 warps/SM)
    pv_gemm<<<dim3(4, 64, 2), 256>>>(pS1, pS2, pVT1, pVT2,
                                     im1, im2, out1, out2, pRinv);
}